// round 2
// baseline (speedup 1.0000x reference)
#include <cuda_runtime.h>
#include <cstdint>

#define D 256
#define G3 768
#define HOR 24
#define ROWS 64
#define THREADS 512
#define RSTR 68            // padded row stride for h tiles (k-major [256][RSTR])
#define NBLK 250

// shared-memory float offsets
#define OFF_HA   0                 // 256*68 = 17408
#define OFF_HB   17408             // 17408
#define OFF_WS   34816             // 3*32*33 = 3168
#define OFF_WIH  37984             // 768
#define OFF_BIH  38752             // 768
#define OFF_BHH  39520             // 768
#define OFF_WL   40288             // 2048
#define OFF_WH   42336             // 8
#define OFF_BL   42344             // 8
#define OFF_X    42352             // 64
#define OFF_LV   42416             // 64
#define OFF_PRED 42480             // 24*64 = 1536
#define OFF_GATE 44016             // 1536
#define SMEM_FLOATS 45552
#define SMEM_BYTES (SMEM_FLOATS * 4)

__device__ __forceinline__ float sigm(float v) {
    return 1.0f / (1.0f + __expf(-v));
}

__global__ __launch_bounds__(THREADS, 1)
void pprm_kernel(const float* __restrict__ feat,
                 const float* __restrict__ lastv,
                 const float* __restrict__ W_ih,
                 const float* __restrict__ W_hh,
                 const float* __restrict__ b_ih,
                 const float* __restrict__ b_hh,
                 const float* __restrict__ Wl,
                 const float* __restrict__ bl,
                 const float* __restrict__ Wh,
                 const float* __restrict__ bh,
                 const float* __restrict__ Wg1,
                 const float* __restrict__ bg1,
                 const float* __restrict__ Wg2,
                 const float* __restrict__ bg2,
                 const float* __restrict__ log_decay,
                 float* __restrict__ out)
{
    extern __shared__ float sm[];
    const int tid = threadIdx.x;
    const int row0g = blockIdx.x * ROWS;

    // GEMM thread mapping: warp-uniform row group, lanes span 32 output dims
    const int dl = tid & 31;        // local output dim within chunk
    const int rg = tid >> 5;        // 0..15
    const int r0 = rg * 4;          // 4 rows per thread

    // pred/gate mapping
    const int part = tid & 7;       // k-split 0..7 (32 dims each)
    const int prow = tid >> 3;      // row 0..63

    const float bh_v = bh[0];
    const float dr   = __expf(log_decay[0]);

    // ---- init: small weights to smem ----
    for (int i = tid; i < G3; i += THREADS) {
        sm[OFF_WIH + i] = W_ih[i];
        sm[OFF_BIH + i] = b_ih[i];
        sm[OFF_BHH + i] = b_hh[i];
    }
    for (int i = tid; i < 8 * D; i += THREADS) sm[OFF_WL + i] = Wl[i];
    if (tid < 8) { sm[OFF_WH + tid] = Wh[tid]; sm[OFF_BL + tid] = bl[tid]; }
    if (tid < ROWS) {
        float lv = lastv[row0g + tid];
        sm[OFF_LV + tid] = lv;
        sm[OFF_X + tid]  = lv;
    }

    // ---- init: features -> hA transposed [k][row] ----
    {
        const float4* f4 = reinterpret_cast<const float4*>(feat + (size_t)row0g * D);
        for (int i = tid; i < ROWS * (D / 4); i += THREADS) {
            int r = i >> 6;          // row
            int q = i & 63;          // float4 index along k
            float4 v = f4[r * 64 + q];
            int k = q * 4;
            sm[OFF_HA + (k    ) * RSTR + r] = v.x;
            sm[OFF_HA + (k + 1) * RSTR + r] = v.y;
            sm[OFF_HA + (k + 2) * RSTR + r] = v.z;
            sm[OFF_HA + (k + 3) * RSTR + r] = v.w;
        }
    }
    __syncthreads();

    // ---- refine gate: gate[t] = sigmoid(relu(feat@Wg1^T+bg1)@Wg2^T+bg2) ----
    {
        float u[8] = {0,0,0,0,0,0,0,0};
        for (int dd = 0; dd < 32; ++dd) {
            int d = part * 32 + dd;
            float hv = sm[OFF_HA + d * RSTR + prow];
            #pragma unroll
            for (int l = 0; l < 8; ++l) u[l] += hv * Wg1[l * D + d];
        }
        #pragma unroll
        for (int l = 0; l < 8; ++l) {
            u[l] += __shfl_xor_sync(0xffffffffu, u[l], 1);
            u[l] += __shfl_xor_sync(0xffffffffu, u[l], 2);
            u[l] += __shfl_xor_sync(0xffffffffu, u[l], 4);
        }
        if (part == 0) {
            #pragma unroll
            for (int l = 0; l < 8; ++l) u[l] = fmaxf(u[l] + bg1[l], 0.0f);
            for (int t = 0; t < HOR; ++t) {
                float s = bg2[t];
                #pragma unroll
                for (int l = 0; l < 8; ++l) s += u[l] * Wg2[t * 8 + l];
                sm[OFF_GATE + t * ROWS + prow] = sigm(s);
            }
        }
    }
    __syncthreads();

    float* hA = sm + OFF_HA;
    float* hB = sm + OFF_HB;

    // ---- 24 autoregressive GRU steps ----
    for (int t = 0; t < HOR; ++t) {
        for (int c = 0; c < 8; ++c) {
            const int d0 = c * 32;
            float accr[4] = {0,0,0,0};
            float accz[4] = {0,0,0,0};
            float accn[4] = {0,0,0,0};

            // prefetch first W tile into registers
            float wv[6];
            #pragma unroll
            for (int m = 0; m < 6; ++m) {
                int i = tid + m * THREADS;
                int j = i >> 5, k = i & 31;
                int g = j >> 5, dd = j & 31;
                wv[m] = W_hh[(g * D + d0 + dd) * D + k];
            }

            for (int kt = 0; kt < 8; ++kt) {
                __syncthreads();   // previous tile fully consumed
                #pragma unroll
                for (int m = 0; m < 6; ++m) {
                    int i = tid + m * THREADS;
                    int j = i >> 5, k = i & 31;
                    int g = j >> 5, dd = j & 31;
                    sm[OFF_WS + (g * 32 + k) * 33 + dd] = wv[m];
                }
                __syncthreads();
                if (kt < 7) {      // prefetch next tile (overlaps compute)
                    #pragma unroll
                    for (int m = 0; m < 6; ++m) {
                        int i = tid + m * THREADS;
                        int j = i >> 5, k = i & 31;
                        int g = j >> 5, dd = j & 31;
                        wv[m] = W_hh[(g * D + d0 + dd) * D + (kt + 1) * 32 + k];
                    }
                }
                const float* hp = hA + (kt * 32) * RSTR + r0;
                const float* wp = sm + OFF_WS + dl;
                #pragma unroll
                for (int kk = 0; kk < 32; ++kk) {
                    float4 h4 = *reinterpret_cast<const float4*>(hp + kk * RSTR);
                    float wr = wp[kk * 33];
                    float wz = wp[kk * 33 + 1056];
                    float wn = wp[kk * 33 + 2112];
                    accr[0] += h4.x * wr; accr[1] += h4.y * wr;
                    accr[2] += h4.z * wr; accr[3] += h4.w * wr;
                    accz[0] += h4.x * wz; accz[1] += h4.y * wz;
                    accz[2] += h4.z * wz; accz[3] += h4.w * wz;
                    accn[0] += h4.x * wn; accn[1] += h4.y * wn;
                    accn[2] += h4.z * wn; accn[3] += h4.w * wn;
                }
            }

            // fused gate epilogue for output dim d = d0+dl, 4 rows
            const int d = d0 + dl;
            const float wri = sm[OFF_WIH + d];
            const float wzi = sm[OFF_WIH + D + d];
            const float wni = sm[OFF_WIH + 2 * D + d];
            const float cr  = sm[OFF_BIH + d]         + sm[OFF_BHH + d];
            const float cz  = sm[OFF_BIH + D + d]     + sm[OFF_BHH + D + d];
            const float bni = sm[OFF_BIH + 2 * D + d];
            const float bnh = sm[OFF_BHH + 2 * D + d];
            #pragma unroll
            for (int i = 0; i < 4; ++i) {
                float x  = sm[OFF_X + r0 + i];
                float r  = sigm(fmaf(x, wri, cr) + accr[i]);
                float z  = sigm(fmaf(x, wzi, cz) + accz[i]);
                float hn = accn[i] + bnh;
                float nn = tanhf(fmaf(x, wni, bni) + r * hn);
                float ho = hA[d * RSTR + r0 + i];
                hB[d * RSTR + r0 + i] = (1.0f - z) * nn + z * ho;
            }
        }
        __syncthreads();  // hB complete; epilogue x_s reads done

        // ---- pred head: (h_new @ Wl^T + bl) @ Wh^T + bh ----
        {
            float low[8] = {0,0,0,0,0,0,0,0};
            for (int dd = 0; dd < 32; ++dd) {
                int d = part * 32 + dd;
                float hv = hB[d * RSTR + prow];
                #pragma unroll
                for (int l = 0; l < 8; ++l) low[l] += hv * sm[OFF_WL + l * D + d];
            }
            #pragma unroll
            for (int l = 0; l < 8; ++l) {
                low[l] += __shfl_xor_sync(0xffffffffu, low[l], 1);
                low[l] += __shfl_xor_sync(0xffffffffu, low[l], 2);
                low[l] += __shfl_xor_sync(0xffffffffu, low[l], 4);
            }
            if (part == 0) {
                float p = bh_v;
                #pragma unroll
                for (int l = 0; l < 8; ++l)
                    p += (low[l] + sm[OFF_BL + l]) * sm[OFF_WH + l];
                sm[OFF_PRED + t * ROWS + prow] = p;
                sm[OFF_X + prow] = p;          // autoregressive feedback
            }
        }
        __syncthreads();

        float* tmp = hA; hA = hB; hB = tmp;
    }

    // ---- blend with decay curve and write output ----
    for (int i = tid; i < ROWS * HOR; i += THREADS) {
        int r = i / HOR;
        int t = i % HOR;
        float g = sm[OFF_GATE + t * ROWS + r];
        float p = sm[OFF_PRED + t * ROWS + r];
        float dcv = sm[OFF_LV + r] * __expf(-dr * (float)(t + 1));
        out[(size_t)(row0g + r) * HOR + t] = g * p + (1.0f - g) * dcv;
    }
}

extern "C" void kernel_launch(void* const* d_in, const int* in_sizes, int n_in,
                              void* d_out, int out_size) {
    const float* feat  = (const float*)d_in[0];
    const float* lastv = (const float*)d_in[1];
    const float* W_ih  = (const float*)d_in[2];
    const float* W_hh  = (const float*)d_in[3];
    const float* b_ih  = (const float*)d_in[4];
    const float* b_hh  = (const float*)d_in[5];
    const float* Wl    = (const float*)d_in[6];
    const float* bl    = (const float*)d_in[7];
    const float* Wh    = (const float*)d_in[8];
    const float* bh    = (const float*)d_in[9];
    const float* Wg1   = (const float*)d_in[10];
    const float* bg1   = (const float*)d_in[11];
    const float* Wg2   = (const float*)d_in[12];
    const float* bg2   = (const float*)d_in[13];
    const float* ldec  = (const float*)d_in[14];
    float* out = (float*)d_out;

    cudaFuncSetAttribute(pprm_kernel,
                         cudaFuncAttributeMaxDynamicSharedMemorySize,
                         SMEM_BYTES);
    pprm_kernel<<<NBLK, THREADS, SMEM_BYTES>>>(
        feat, lastv, W_ih, W_hh, b_ih, b_hh, Wl, bl, Wh, bh,
        Wg1, bg1, Wg2, bg2, ldec, out);
}

// round 3
// speedup vs baseline: 1.0797x; 1.0797x over previous
#include <cuda_runtime.h>
#include <cstdint>

#define D 256
#define G3 768
#define HOR 24
#define ROWS 64
#define THREADS 512
#define RSTR 68            // padded row stride for h tiles (k-major [256][RSTR])
#define NBLK 250
#define WSB 6336           // floats per W staging buffer: 3*32*66

// shared-memory float offsets
#define OFF_HA   0                 // 256*68 = 17408
#define OFF_HB   17408             // 17408
#define OFF_WS   34816             // 2 * 6336 = 12672 (double-buffered)
#define OFF_WIH  47488             // 768
#define OFF_BIH  48256             // 768
#define OFF_BHH  49024             // 768
#define OFF_WL   49792             // 2048
#define OFF_WH   51840             // 8
#define OFF_BL   51848             // 8
#define OFF_X    51856             // 64
#define OFF_LV   51920             // 64
#define OFF_PRED 51984             // 24*64 = 1536
#define OFF_GATE 53520             // 1536
#define SMEM_FLOATS 55056
#define SMEM_BYTES (SMEM_FLOATS * 4)   // 220224 B

typedef unsigned long long ull;

__device__ __forceinline__ float sigm(float v) {
    return 1.0f / (1.0f + __expf(-v));
}

__device__ __forceinline__ ull dup_f32x2(float x) {
    ull r;
    asm("mov.b64 %0, {%1, %1};" : "=l"(r) : "r"(__float_as_uint(x)));
    return r;
}

__device__ __forceinline__ void fma2(ull& acc, ull a, ull b) {
    asm("fma.rn.f32x2 %0, %1, %2, %0;" : "+l"(acc) : "l"(a), "l"(b));
}

// stage one 3x32x64 W tile (6144 floats) into smem via cp.async (4B each, 12/thread)
__device__ __forceinline__ void issue_tile(const float* __restrict__ W_hh,
                                           uint32_t ws_u32, int d0, int kbase,
                                           int tid) {
    const int k  = tid & 31;
    const int jb = tid >> 5;
    #pragma unroll
    for (int m = 0; m < 12; ++m) {
        int j  = jb + m * 16;      // 0..191
        int dd = j & 63;
        int g  = j >> 6;           // 0..2
        const float* src = W_hh + (((g << 8) + d0 + dd) << 8) + kbase + k;
        uint32_t dst = ws_u32 + ((((g * 32 + k) * 66) + dd) << 2);
        asm volatile("cp.async.ca.shared.global [%0], [%1], 4;\n"
                     :: "r"(dst), "l"(src));
    }
    asm volatile("cp.async.commit_group;\n" ::: "memory");
}

__global__ __launch_bounds__(THREADS, 1)
void pprm_kernel(const float* __restrict__ feat,
                 const float* __restrict__ lastv,
                 const float* __restrict__ W_ih,
                 const float* __restrict__ W_hh,
                 const float* __restrict__ b_ih,
                 const float* __restrict__ b_hh,
                 const float* __restrict__ Wl,
                 const float* __restrict__ bl,
                 const float* __restrict__ Wh,
                 const float* __restrict__ bh,
                 const float* __restrict__ Wg1,
                 const float* __restrict__ bg1,
                 const float* __restrict__ Wg2,
                 const float* __restrict__ bg2,
                 const float* __restrict__ log_decay,
                 float* __restrict__ out)
{
    extern __shared__ float sm[];
    const int tid = threadIdx.x;
    const int row0g = blockIdx.x * ROWS;

    // GEMM mapping: lane dl owns output dims (d0+2*dl, d0+2*dl+1); rg owns 4 rows
    const int dl = tid & 31;
    const int rg = tid >> 5;        // 0..15
    const int r0 = rg * 4;

    // pred/gate mapping
    const int part = tid & 7;       // k-split 0..7 (32 dims each)
    const int prow = tid >> 3;      // row 0..63

    const float bh_v = bh[0];
    const float dr   = __expf(log_decay[0]);

    const uint32_t ws_u32 =
        (uint32_t)__cvta_generic_to_shared(sm + OFF_WS);

    // ---- init: small weights to smem ----
    for (int i = tid; i < G3; i += THREADS) {
        sm[OFF_WIH + i] = W_ih[i];
        sm[OFF_BIH + i] = b_ih[i];
        sm[OFF_BHH + i] = b_hh[i];
    }
    for (int i = tid; i < 8 * D; i += THREADS) sm[OFF_WL + i] = Wl[i];
    if (tid < 8) { sm[OFF_WH + tid] = Wh[tid]; sm[OFF_BL + tid] = bl[tid]; }
    if (tid < ROWS) {
        float lv = lastv[row0g + tid];
        sm[OFF_LV + tid] = lv;
        sm[OFF_X + tid]  = lv;
    }

    // ---- init: features -> hA transposed [k][row] ----
    {
        const float4* f4 = reinterpret_cast<const float4*>(feat + (size_t)row0g * D);
        for (int i = tid; i < ROWS * (D / 4); i += THREADS) {
            int r = i >> 6;          // row
            int q = i & 63;          // float4 index along k
            float4 v = f4[r * 64 + q];
            int k = q * 4;
            sm[OFF_HA + (k    ) * RSTR + r] = v.x;
            sm[OFF_HA + (k + 1) * RSTR + r] = v.y;
            sm[OFF_HA + (k + 2) * RSTR + r] = v.z;
            sm[OFF_HA + (k + 3) * RSTR + r] = v.w;
        }
    }
    __syncthreads();

    // ---- refine gate ----
    {
        float u[8] = {0,0,0,0,0,0,0,0};
        for (int dd = 0; dd < 32; ++dd) {
            int d = part * 32 + dd;
            float hv = sm[OFF_HA + d * RSTR + prow];
            #pragma unroll
            for (int l = 0; l < 8; ++l) u[l] += hv * Wg1[l * D + d];
        }
        #pragma unroll
        for (int l = 0; l < 8; ++l) {
            u[l] += __shfl_xor_sync(0xffffffffu, u[l], 1);
            u[l] += __shfl_xor_sync(0xffffffffu, u[l], 2);
            u[l] += __shfl_xor_sync(0xffffffffu, u[l], 4);
        }
        if (part == 0) {
            #pragma unroll
            for (int l = 0; l < 8; ++l) u[l] = fmaxf(u[l] + bg1[l], 0.0f);
            for (int t = 0; t < HOR; ++t) {
                float s = bg2[t];
                #pragma unroll
                for (int l = 0; l < 8; ++l) s += u[l] * Wg2[t * 8 + l];
                sm[OFF_GATE + t * ROWS + prow] = sigm(s);
            }
        }
    }
    __syncthreads();

    float* hA = sm + OFF_HA;
    float* hB = sm + OFF_HB;

    // ---- 24 autoregressive GRU steps ----
    for (int t = 0; t < HOR; ++t) {
        for (int c = 0; c < 4; ++c) {
            const int d0 = c * 64;

            // packed accumulators: [gate][row], halves = 2 output dims
            ull accr[4] = {0,0,0,0};
            ull accz[4] = {0,0,0,0};
            ull accn[4] = {0,0,0,0};

            issue_tile(W_hh, ws_u32, d0, 0, tid);       // tile 0 -> buf 0

            for (int kt = 0; kt < 8; ++kt) {
                if (kt < 7) {
                    issue_tile(W_hh, ws_u32 + ((kt + 1) & 1) * (WSB * 4),
                               d0, (kt + 1) * 32, tid);
                    asm volatile("cp.async.wait_group 1;\n" ::: "memory");
                } else {
                    asm volatile("cp.async.wait_group 0;\n" ::: "memory");
                }
                __syncthreads();   // tile kt visible to all; prev compute done

                const float* ws = sm + OFF_WS + (kt & 1) * WSB + 2 * dl;
                const float* hp = hA + (kt * 32) * RSTR + r0;
                #pragma unroll
                for (int kk = 0; kk < 32; ++kk) {
                    float4 h4 = *reinterpret_cast<const float4*>(hp + kk * RSTR);
                    ull h0 = dup_f32x2(h4.x);
                    ull h1 = dup_f32x2(h4.y);
                    ull h2 = dup_f32x2(h4.z);
                    ull h3 = dup_f32x2(h4.w);
                    ull wr = *reinterpret_cast<const ull*>(ws + kk * 66);
                    ull wz = *reinterpret_cast<const ull*>(ws + kk * 66 + 2112);
                    ull wn = *reinterpret_cast<const ull*>(ws + kk * 66 + 4224);
                    fma2(accr[0], h0, wr); fma2(accr[1], h1, wr);
                    fma2(accr[2], h2, wr); fma2(accr[3], h3, wr);
                    fma2(accz[0], h0, wz); fma2(accz[1], h1, wz);
                    fma2(accz[2], h2, wz); fma2(accz[3], h3, wz);
                    fma2(accn[0], h0, wn); fma2(accn[1], h1, wn);
                    fma2(accn[2], h2, wn); fma2(accn[3], h3, wn);
                }
                __syncthreads();   // all compute on buf[kt&1] done before reuse
            }

            // fused gate epilogue: 2 dims x 4 rows per thread
            #pragma unroll
            for (int p = 0; p < 2; ++p) {
                const int d = d0 + 2 * dl + p;
                const float wri = sm[OFF_WIH + d];
                const float wzi = sm[OFF_WIH + D + d];
                const float wni = sm[OFF_WIH + 2 * D + d];
                const float cr  = sm[OFF_BIH + d]         + sm[OFF_BHH + d];
                const float cz  = sm[OFF_BIH + D + d]     + sm[OFF_BHH + D + d];
                const float bni = sm[OFF_BIH + 2 * D + d];
                const float bnh = sm[OFF_BHH + 2 * D + d];
                #pragma unroll
                for (int i = 0; i < 4; ++i) {
                    float ar = (p == 0) ? __uint_as_float((uint32_t)accr[i])
                                        : __uint_as_float((uint32_t)(accr[i] >> 32));
                    float az = (p == 0) ? __uint_as_float((uint32_t)accz[i])
                                        : __uint_as_float((uint32_t)(accz[i] >> 32));
                    float an = (p == 0) ? __uint_as_float((uint32_t)accn[i])
                                        : __uint_as_float((uint32_t)(accn[i] >> 32));
                    float x  = sm[OFF_X + r0 + i];
                    float r  = sigm(fmaf(x, wri, cr) + ar);
                    float z  = sigm(fmaf(x, wzi, cz) + az);
                    float hn = an + bnh;
                    float nn = tanhf(fmaf(x, wni, bni) + r * hn);
                    float ho = hA[d * RSTR + r0 + i];
                    hB[d * RSTR + r0 + i] = (1.0f - z) * nn + z * ho;
                }
            }
        }
        __syncthreads();  // hB complete

        // ---- pred head: (h_new @ Wl^T + bl) @ Wh^T + bh ----
        {
            float low[8] = {0,0,0,0,0,0,0,0};
            for (int dd = 0; dd < 32; ++dd) {
                int d = part * 32 + dd;
                float hv = hB[d * RSTR + prow];
                #pragma unroll
                for (int l = 0; l < 8; ++l) low[l] += hv * sm[OFF_WL + l * D + d];
            }
            #pragma unroll
            for (int l = 0; l < 8; ++l) {
                low[l] += __shfl_xor_sync(0xffffffffu, low[l], 1);
                low[l] += __shfl_xor_sync(0xffffffffu, low[l], 2);
                low[l] += __shfl_xor_sync(0xffffffffu, low[l], 4);
            }
            if (part == 0) {
                float p = bh_v;
                #pragma unroll
                for (int l = 0; l < 8; ++l)
                    p += (low[l] + sm[OFF_BL + l]) * sm[OFF_WH + l];
                sm[OFF_PRED + t * ROWS + prow] = p;
                sm[OFF_X + prow] = p;          // autoregressive feedback
            }
        }
        __syncthreads();

        float* tmp = hA; hA = hB; hB = tmp;
    }

    // ---- blend with decay curve and write output ----
    for (int i = tid; i < ROWS * HOR; i += THREADS) {
        int r = i / HOR;
        int t = i % HOR;
        float g = sm[OFF_GATE + t * ROWS + r];
        float p = sm[OFF_PRED + t * ROWS + r];
        float dcv = sm[OFF_LV + r] * __expf(-dr * (float)(t + 1));
        out[(size_t)(row0g + r) * HOR + t] = g * p + (1.0f - g) * dcv;
    }
}

extern "C" void kernel_launch(void* const* d_in, const int* in_sizes, int n_in,
                              void* d_out, int out_size) {
    const float* feat  = (const float*)d_in[0];
    const float* lastv = (const float*)d_in[1];
    const float* W_ih  = (const float*)d_in[2];
    const float* W_hh  = (const float*)d_in[3];
    const float* b_ih  = (const float*)d_in[4];
    const float* b_hh  = (const float*)d_in[5];
    const float* Wl    = (const float*)d_in[6];
    const float* bl    = (const float*)d_in[7];
    const float* Wh    = (const float*)d_in[8];
    const float* bh    = (const float*)d_in[9];
    const float* Wg1   = (const float*)d_in[10];
    const float* bg1   = (const float*)d_in[11];
    const float* Wg2   = (const float*)d_in[12];
    const float* bg2   = (const float*)d_in[13];
    const float* ldec  = (const float*)d_in[14];
    float* out = (float*)d_out;

    cudaFuncSetAttribute(pprm_kernel,
                         cudaFuncAttributeMaxDynamicSharedMemorySize,
                         SMEM_BYTES);
    pprm_kernel<<<NBLK, THREADS, SMEM_BYTES>>>(
        feat, lastv, W_ih, W_hh, b_ih, b_hh, Wl, bl, Wh, bh,
        Wg1, bg1, Wg2, bg2, ldec, out);
}